// round 15
// baseline (speedup 1.0000x reference)
#include <cuda_runtime.h>
#include <cuda_bf16.h>
#include <cuda_fp16.h>
#include <cstdint>

#define S_   2048
#define SM_  2047
#define NEGV (-1e9f)

// Output layout (floats): poi, time, dist, attn1, attn2, attn3
#define O_POI   ((size_t)0)
#define O_TIME  ((size_t)2097152)
#define O_DIST  ((size_t)4193280)
#define O_A1    ((size_t)6289408)
#define O_A2    ((size_t)73398272)
#define O_A3    ((size_t)140441616)

// fp16 logits / softmax scratch: [z][2048][2048], zero padded
__device__ __align__(16) __half g_p[(size_t)3 * 16 * 2048 * 2048];
// pre-split Q,K: [z][2048 rows][ qh(64) | ql(64) ] bf16, zero padded rows
__device__ __align__(16) __nv_bfloat16 g_q[(size_t)48 * 2048 * 128];
__device__ __align__(16) __nv_bfloat16 g_k[(size_t)48 * 2048 * 128];
// V fp16: [z][2048 rows][64], zero padded rows
__device__ __align__(16) __half g_v[(size_t)48 * 2048 * 64];

// ---------------- helpers ----------------
__device__ __forceinline__ uint32_t smem_u32(const void* p) {
    uint32_t a;
    asm("{ .reg .u64 t; cvta.to.shared.u64 t, %1; cvt.u32.u64 %0, t; }" : "=r"(a) : "l"(p));
    return a;
}
__device__ __forceinline__ void cpa16(uint32_t d, const void* g) {
    asm volatile("cp.async.cg.shared.global [%0], [%1], 16;" :: "r"(d), "l"(g));
}
__device__ __forceinline__ void cpa_commit() {
    asm volatile("cp.async.commit_group;");
}
__device__ __forceinline__ void cpa_wait_all() {
    asm volatile("cp.async.commit_group;");
    asm volatile("cp.async.wait_group 0;");
}
__device__ __forceinline__ void ldm4(uint32_t* r, uint32_t addr) {
    asm volatile("ldmatrix.sync.aligned.m8n8.x4.shared.b16 {%0,%1,%2,%3}, [%4];"
                 : "=r"(r[0]), "=r"(r[1]), "=r"(r[2]), "=r"(r[3]) : "r"(addr));
}
__device__ __forceinline__ void ldm4t(uint32_t* r, uint32_t addr) {
    asm volatile("ldmatrix.sync.aligned.m8n8.x4.trans.shared.b16 {%0,%1,%2,%3}, [%4];"
                 : "=r"(r[0]), "=r"(r[1]), "=r"(r[2]), "=r"(r[3]) : "r"(addr));
}
__device__ __forceinline__ void mma_bf16(float* c, const uint32_t* a, const uint32_t* b) {
    asm volatile("mma.sync.aligned.m16n8k16.row.col.f32.bf16.bf16.f32 "
                 "{%0,%1,%2,%3}, {%4,%5,%6,%7}, {%8,%9}, {%0,%1,%2,%3};"
                 : "+f"(c[0]), "+f"(c[1]), "+f"(c[2]), "+f"(c[3])
                 : "r"(a[0]), "r"(a[1]), "r"(a[2]), "r"(a[3]), "r"(b[0]), "r"(b[1]));
}
__device__ __forceinline__ void mma_f16(float* c, const uint32_t* a, const uint32_t* b) {
    asm volatile("mma.sync.aligned.m16n8k16.row.col.f32.f16.f16.f32 "
                 "{%0,%1,%2,%3}, {%4,%5,%6,%7}, {%8,%9}, {%0,%1,%2,%3};"
                 : "+f"(c[0]), "+f"(c[1]), "+f"(c[2]), "+f"(c[3])
                 : "r"(a[0]), "r"(a[1]), "r"(a[2]), "r"(a[3]), "r"(b[0]), "r"(b[1]));
}
__device__ __forceinline__ void split2(float a, float b, uint32_t& hi, uint32_t& lo) {
    __nv_bfloat16 ha = __float2bfloat16(a), hb = __float2bfloat16(b);
    float la = a - __bfloat162float(ha), lb = b - __bfloat162float(hb);
    __nv_bfloat162 hh; hh.x = ha; hh.y = hb;
    hi = *reinterpret_cast<uint32_t*>(&hh);
    __nv_bfloat162 ll = __floats2bfloat162_rn(la, lb);
    lo = *reinterpret_cast<uint32_t*>(&ll);
}
__device__ __forceinline__ uint32_t ph2(float a, float b) {
    __half2 h = __floats2half2_rn(a, b);
    return *reinterpret_cast<uint32_t*>(&h);
}

// ---------------------------------------------------------------------------
// K0: conversion (unchanged).
// ---------------------------------------------------------------------------
__global__ __launch_bounds__(256) void convert_kernel(
    const float* __restrict__ pq, const float* __restrict__ pk, const float* __restrict__ pvv,
    const float* __restrict__ tq, const float* __restrict__ tk, const float* __restrict__ tvv,
    const float* __restrict__ dq, const float* __restrict__ dk, const float* __restrict__ dvv)
{
    int gid = blockIdx.x * 256 + threadIdx.x;
    int c4  = gid & 15;
    int row = (gid >> 4) & 2047;
    int z   = gid >> 15;
    int s = z >> 4, bh = z & 15;

    const float *q, *k, *v;
    int Sq;
    if (s == 0)      { q = pq; k = pk; v = pvv; Sq = S_;  }
    else if (s == 1) { q = tq; k = tk; v = tvv; Sq = SM_; }
    else             { q = dq; k = dk; v = dvv; Sq = SM_; }

    float4 qv = make_float4(0.f,0.f,0.f,0.f), kv = qv, vv = qv;
    if (row < Sq) {
        size_t in = ((size_t)bh * Sq + row) * 64 + c4 * 4;
        qv = *(const float4*)(q + in);
        kv = *(const float4*)(k + in);
        vv = *(const float4*)(v + in);
        qv.x *= 0.125f; qv.y *= 0.125f; qv.z *= 0.125f; qv.w *= 0.125f;
    }
    size_t base = ((size_t)z * 2048 + row) * 128 + c4 * 4;
    uint32_t h01, h23, l01, l23;
    split2(qv.x, qv.y, h01, l01); split2(qv.z, qv.w, h23, l23);
    *(uint2*)(g_q + base)      = make_uint2(h01, h23);
    *(uint2*)(g_q + base + 64) = make_uint2(l01, l23);
    split2(kv.x, kv.y, h01, l01); split2(kv.z, kv.w, h23, l23);
    *(uint2*)(g_k + base)      = make_uint2(h01, h23);
    *(uint2*)(g_k + base + 64) = make_uint2(l01, l23);
    *(uint2*)(g_v + ((size_t)z * 2048 + row) * 64 + c4 * 4) =
        make_uint2(ph2(vv.x, vv.y), ph2(vv.z, vv.w));
}

// ---------------------------------------------------------------------------
// K1: logits -> fp16 g_p. 512 threads, 4x4 warp grid, 32x32 per warp.
// Same 128x128 tile and 69632B smem; 32 warps/SM at 2 blocks/SM.
// ---------------------------------------------------------------------------
__global__ __launch_bounds__(512, 2) void qk_kernel()
{
    extern __shared__ __align__(16) char smc[];
    const uint32_t sb = smem_u32(smc);
    const uint32_t sbB = sb + 34816;

    const int tid = threadIdx.x, lid = tid & 31, wid = tid >> 5;
    const int z = blockIdx.z, s = z >> 4;
    const int Sq = s ? SM_ : S_;
    const int m0 = blockIdx.y * 128, n0 = blockIdx.x * 128;

    __half* Pout = g_p + ((size_t)z << 22);
    const __nv_bfloat16* Qs = g_q + ((size_t)z * 2048 + m0) * 128;
    const __nv_bfloat16* Ks = g_k + ((size_t)z * 2048 + n0) * 128;

    #pragma unroll
    for (int it = 0; it < 4; ++it) {
        int i = it * 512 + tid;
        int r = i >> 4, c = i & 15;
        cpa16(sb  + r * 272 + c * 16, Qs + (size_t)r * 128 + c * 8);
        cpa16(sbB + r * 272 + c * 16, Ks + (size_t)r * 128 + c * 8);
    }
    cpa_wait_all();
    __syncthreads();

    const int wm = wid & 3, wn = wid >> 2;   // 4x4 warps: 32m x 32n each
    float acc[8][4];
    #pragma unroll
    for (int t = 0; t < 8; ++t)
        #pragma unroll
        for (int j = 0; j < 4; ++j) acc[t][j] = 0.f;

    #pragma unroll
    for (int term = 0; term < 3; ++term) {
        const uint32_t aoff = (term == 2) ? 128u : 0u;
        const uint32_t boff = (term == 1) ? 128u : 0u;
        #pragma unroll
        for (int ks = 0; ks < 4; ++ks) {
            uint32_t a[2][4];
            #pragma unroll
            for (int mi = 0; mi < 2; ++mi) {
                int row = wm * 32 + mi * 16 + (lid & 15);
                ldm4(a[mi], sb + row * 272 + aoff + ks * 32 + ((lid >> 4) << 4));
            }
            uint32_t b[4][2];
            #pragma unroll
            for (int nb2 = 0; nb2 < 2; ++nb2) {
                int row = wn * 32 + nb2 * 16 + ((lid >> 4) << 3) + (lid & 7);
                uint32_t r4[4];
                ldm4(r4, sbB + row * 272 + boff + ks * 32 + (((lid >> 3) & 1) << 4));
                b[nb2 * 2][0] = r4[0]; b[nb2 * 2][1] = r4[1];
                b[nb2 * 2 + 1][0] = r4[2]; b[nb2 * 2 + 1][1] = r4[3];
            }
            #pragma unroll
            for (int mi = 0; mi < 2; ++mi)
                #pragma unroll
                for (int nj = 0; nj < 4; ++nj)
                    mma_bf16(acc[mi * 4 + nj], a[mi], b[nj]);
        }
    }

    const int lrow = lid >> 2, lcol = (lid & 3) * 2;
    #pragma unroll
    for (int mi = 0; mi < 2; ++mi) {
        #pragma unroll
        for (int h = 0; h < 2; ++h) {
            int q = m0 + wm * 32 + mi * 16 + h * 8 + lrow;
            if (q >= Sq) continue;
            __half* prow = Pout + ((size_t)q << 11);
            #pragma unroll
            for (int nj = 0; nj < 4; ++nj) {
                int cg = n0 + wn * 32 + nj * 8 + lcol;
                *(uint32_t*)(prow + cg) =
                    ph2(acc[mi * 4 + nj][h * 2], acc[mi * 4 + nj][h * 2 + 1]);
            }
        }
    }
}

// ---------------------------------------------------------------------------
// K2: softmax (unchanged from R13).
// ---------------------------------------------------------------------------
__global__ __launch_bounds__(256) void softmax_kernel(
    const int* __restrict__ mask, float* __restrict__ out)
{
    const int row = blockIdx.x, z = blockIdx.y, stream = z >> 4, bh = z & 15;
    int Sk; float* A;
    if (stream == 0)      { Sk = S_;  A = out + O_A1 + (size_t)bh * S_  * S_;  }
    else if (stream == 1) { Sk = SM_; A = out + O_A2 + (size_t)bh * SM_ * SM_; }
    else                  { Sk = SM_; A = out + O_A3 + (size_t)bh * SM_ * SM_; }

    const int tid = threadIdx.x;
    __half* r16 = g_p + ((size_t)z << 22) + ((size_t)row << 11);

    if (row >= Sk) {
        ((uint4*)r16)[tid] = make_uint4(0, 0, 0, 0);
        return;
    }

    float* r = A + (size_t)row * Sk;
    const bool vec = (stream == 0);
    const int i0 = tid * 8;
    float v[8];
    if (vec) {
        uint4 hv = *(const uint4*)(r16 + i0);
        const __half2* hp = (const __half2*)&hv;
        #pragma unroll
        for (int u = 0; u < 4; ++u) {
            float2 f = __half22float2(hp[u]);
            v[u * 2] = f.x; v[u * 2 + 1] = f.y;
        }
        const int* Mrow = mask + ((size_t)(bh >> 3) << 22) + ((size_t)row << 11) + i0;
        int4 ma = *(const int4*)Mrow;
        int4 mb = *(const int4*)(Mrow + 4);
        if (!ma.x) v[0] = NEGV; if (!ma.y) v[1] = NEGV;
        if (!ma.z) v[2] = NEGV; if (!ma.w) v[3] = NEGV;
        if (!mb.x) v[4] = NEGV; if (!mb.y) v[5] = NEGV;
        if (!mb.z) v[6] = NEGV; if (!mb.w) v[7] = NEGV;
    } else {
        #pragma unroll
        for (int u = 0; u < 8; ++u) {
            int i = u * 256 + tid;
            v[u] = (i < Sk) ? __half2float(r16[i]) : -3.0e38f;
        }
    }

    float m = v[0];
    #pragma unroll
    for (int u = 1; u < 8; ++u) m = fmaxf(m, v[u]);
    #pragma unroll
    for (int o = 16; o > 0; o >>= 1) m = fmaxf(m, __shfl_xor_sync(0xffffffffu, m, o));
    __shared__ float smr[8];
    const int w = tid >> 5, l = tid & 31;
    if (l == 0) smr[w] = m;
    __syncthreads();
    if (tid < 32) {
        float t = (tid < 8) ? smr[tid] : -3.0e38f;
        #pragma unroll
        for (int o = 4; o > 0; o >>= 1) t = fmaxf(t, __shfl_xor_sync(0xffffffffu, t, o));
        if (tid == 0) smr[0] = t;
    }
    __syncthreads();
    m = smr[0];
    __syncthreads();
    float sacc = 0.f;
    #pragma unroll
    for (int u = 0; u < 8; ++u) { v[u] = __expf(v[u] - m); sacc += v[u]; }
    #pragma unroll
    for (int o = 16; o > 0; o >>= 1) sacc += __shfl_xor_sync(0xffffffffu, sacc, o);
    if (l == 0) smr[w] = sacc;
    __syncthreads();
    if (tid < 32) {
        float t = (tid < 8) ? smr[tid] : 0.f;
        #pragma unroll
        for (int o = 4; o > 0; o >>= 1) t += __shfl_xor_sync(0xffffffffu, t, o);
        if (tid == 0) smr[0] = t;
    }
    __syncthreads();
    const float inv = 1.0f / smr[0];
    #pragma unroll
    for (int u = 0; u < 8; ++u) v[u] *= inv;

    if (vec) {
        *(float4*)(r + i0)     = make_float4(v[0], v[1], v[2], v[3]);
        *(float4*)(r + i0 + 4) = make_float4(v[4], v[5], v[6], v[7]);
        uint4 hw;
        hw.x = ph2(v[0], v[1]); hw.y = ph2(v[2], v[3]);
        hw.z = ph2(v[4], v[5]); hw.w = ph2(v[6], v[7]);
        *(uint4*)(r16 + i0) = hw;
    } else {
        #pragma unroll
        for (int u = 0; u < 8; ++u) {
            int i = u * 256 + tid;
            r16[i] = __float2half_rn(v[u]);
            if (i < Sk) r[i] = v[u];
        }
    }
}

// ---------------------------------------------------------------------------
// K3a: jobs 0..2, single chain O = P@V, double-buffered cp.async pipeline.
// ---------------------------------------------------------------------------
__global__ __launch_bounds__(256, 2) void pv_a_kernel(float* __restrict__ out)
{
    extern __shared__ __align__(16) char ps[];
    const uint32_t base = smem_u32(ps);

    const int tid = threadIdx.x, lid = tid & 31, wid = tid >> 5;
    const int z = blockIdx.z, jt = z >> 4, bh = z & 15;
    const int m0 = blockIdx.x * 128;

    const __half* Ph = g_p + ((size_t)(jt * 16 + bh) << 22);
    const __half* Vh = g_v + ((size_t)(jt * 16 + bh) << 17);

    float* O;
    int Sq;
    if (jt == 0)      { O = out + O_POI  + (size_t)bh * S_  * 64; Sq = S_;  }
    else if (jt == 1) { O = out + O_TIME + (size_t)bh * SM_ * 64; Sq = SM_; }
    else              { O = out + O_DIST + (size_t)bh * SM_ * 64; Sq = SM_; }

    const int wm = wid & 3, wn = wid >> 2;

    auto issue = [&](int s, int ck) {
        uint32_t uA = base + s * 27648, uV = uA + 18432;
        #pragma unroll
        for (int it = 0; it < 4; ++it) {
            int i = it * 256 + tid;
            int row = i >> 3, c8 = i & 7;
            cpa16(uA + row * 144 + c8 * 16,
                  Ph + (((size_t)(m0 + row)) << 11) + ck + c8 * 8);
        }
        #pragma unroll
        for (int it = 0; it < 2; ++it) {
            int i = it * 256 + tid;
            int row = i >> 3, c8 = i & 7;
            cpa16(uV + row * 144 + c8 * 16,
                  Vh + (size_t)(ck + row) * 64 + c8 * 8);
        }
        cpa_commit();
    };

    float acc[8][4];
    #pragma unroll
    for (int t = 0; t < 8; ++t)
        #pragma unroll
        for (int j = 0; j < 4; ++j) acc[t][j] = 0.f;

    issue(0, 0);
    issue(1, 64);

    for (int i = 0; i < 32; ++i) {
        if (i < 31) asm volatile("cp.async.wait_group 1;");
        else        asm volatile("cp.async.wait_group 0;");
        __syncthreads();

        const uint32_t uA = base + (i & 1) * 27648, uV = uA + 18432;
        #pragma unroll
        for (int ks = 0; ks < 4; ++ks) {
            uint32_t b[4][2];
            #pragma unroll
            for (int nb2 = 0; nb2 < 2; ++nb2) {
                int krow = ks * 16 + (((lid >> 3) & 1) << 3) + (lid & 7);
                int ncol = wn * 32 + nb2 * 16 + ((lid >> 4) << 3);
                uint32_t r4[4];
                ldm4t(r4, uV + krow * 144 + ncol * 2);
                b[nb2 * 2][0] = r4[0]; b[nb2 * 2][1] = r4[1];
                b[nb2 * 2 + 1][0] = r4[2]; b[nb2 * 2 + 1][1] = r4[3];
            }
            uint32_t a[2][4];
            #pragma unroll
            for (int mi = 0; mi < 2; ++mi) {
                int row = wm * 32 + mi * 16 + (lid & 15);
                ldm4(a[mi], uA + row * 144 + ks * 32 + ((lid >> 4) << 4));
            }
            #pragma unroll
            for (int mi = 0; mi < 2; ++mi)
                #pragma unroll
                for (int nj = 0; nj < 4; ++nj)
                    mma_f16(acc[mi * 4 + nj], a[mi], b[nj]);
        }
        __syncthreads();
        if (i + 2 < 32) issue(i & 1, (i + 2) * 64);
    }

    const int lrow = lid >> 2, lcol = (lid & 3) * 2;
    #pragma unroll
    for (int mi = 0; mi < 2; ++mi) {
        #pragma unroll
        for (int h = 0; h < 2; ++h) {
            int r = m0 + wm * 32 + mi * 16 + h * 8 + lrow;
            if (r >= Sq) continue;
            float* orow = O + (size_t)r * 64;
            #pragma unroll
            for (int nj = 0; nj < 4; ++nj) {
                int cg = wn * 32 + nj * 8 + lcol;
                *(float2*)(orow + cg) =
                    make_float2(acc[mi * 4 + nj][h * 2], acc[mi * 4 + nj][h * 2 + 1]);
            }
        }
    }
}

// ---------------------------------------------------------------------------
// K3b: cross term (unchanged from R14).
// ---------------------------------------------------------------------------
__global__ __launch_bounds__(256, 2) void pv_b_kernel(float* __restrict__ out)
{
    extern __shared__ __align__(16) char ps[];
    const uint32_t base = smem_u32(ps);

    const int tid = threadIdx.x, lid = tid & 31, wid = tid >> 5;
    const int bh = blockIdx.z;
    const int m0 = blockIdx.x * 128;

    const __half* P2h = g_p + ((size_t)(16 + bh) << 22);
    const __half* P3h = g_p + ((size_t)(32 + bh) << 22);
    const __half* Vh  = g_v + ((size_t)bh << 17);
    float* O = out + O_POI + (size_t)bh * S_ * 64;

    const int wm = wid & 3, wn = wid >> 2;

    auto issue = [&](int s, int ck) {
        uint32_t uA2 = base + s * 46080, uA3 = uA2 + 18432, uV = uA2 + 36864;
        #pragma unroll
        for (int it = 0; it < 4; ++it) {
            int i = it * 256 + tid;
            int row = i >> 3, c8 = i & 7;
            int gr = m0 + row - 1;
            size_t roff = ((size_t)(gr < 0 ? 2047 : gr) << 11) + ck + c8 * 8;
            cpa16(uA2 + row * 144 + c8 * 16, P2h + roff);
            cpa16(uA3 + row * 144 + c8 * 16, P3h + roff);
        }
        #pragma unroll
        for (int it = 0; it < 2; ++it) {
            int i = it * 256 + tid;
            int row = i >> 3, c8 = i & 7;
            cpa16(uV + row * 144 + c8 * 16,
                  Vh + (size_t)(ck + row) * 64 + c8 * 8);
        }
        cpa_commit();
    };

    float acc[8][4];
    #pragma unroll
    for (int t = 0; t < 8; ++t)
        #pragma unroll
        for (int j = 0; j < 4; ++j) acc[t][j] = 0.f;

    issue(0, 0);
    issue(1, 64);

    for (int i = 0; i < 32; ++i) {
        if (i < 31) asm volatile("cp.async.wait_group 1;");
        else        asm volatile("cp.async.wait_group 0;");
        __syncthreads();

        const uint32_t uA2 = base + (i & 1) * 46080, uA3 = uA2 + 18432, uV = uA2 + 36864;
        #pragma unroll
        for (int ks = 0; ks < 4; ++ks) {
            uint32_t b[4][2];
            #pragma unroll
            for (int nb2 = 0; nb2 < 2; ++nb2) {
                int krow = ks * 16 + (((lid >> 3) & 1) << 3) + (lid & 7);
                int ncol = wn * 32 + nb2 * 16 + ((lid >> 4) << 3);
                uint32_t r4[4];
                ldm4t(r4, uV + krow * 144 + ncol * 2);
                b[nb2 * 2][0] = r4[0]; b[nb2 * 2][1] = r4[1];
                b[nb2 * 2 + 1][0] = r4[2]; b[nb2 * 2 + 1][1] = r4[3];
            }
            uint32_t a[2][4];
            #pragma unroll
            for (int mi = 0; mi < 2; ++mi) {
                int row = wm * 32 + mi * 16 + (lid & 15);
                ldm4(a[mi], uA2 + row * 144 + ks * 32 + ((lid >> 4) << 4));
            }
            #pragma unroll
            for (int mi = 0; mi < 2; ++mi)
                #pragma unroll
                for (int nj = 0; nj < 4; ++nj)
                    mma_f16(acc[mi * 4 + nj], a[mi], b[nj]);
            #pragma unroll
            for (int mi = 0; mi < 2; ++mi) {
                int row = wm * 32 + mi * 16 + (lid & 15);
                ldm4(a[mi], uA3 + row * 144 + ks * 32 + ((lid >> 4) << 4));
            }
            #pragma unroll
            for (int mi = 0; mi < 2; ++mi)
                #pragma unroll
                for (int nj = 0; nj < 4; ++nj)
                    mma_f16(acc[mi * 4 + nj], a[mi], b[nj]);
        }
        __syncthreads();
        if (i + 2 < 32) issue(i & 1, (i + 2) * 64);
    }

    const int lrow = lid >> 2, lcol = (lid & 3) * 2;
    #pragma unroll
    for (int mi = 0; mi < 2; ++mi) {
        #pragma unroll
        for (int h = 0; h < 2; ++h) {
            int r = m0 + wm * 32 + mi * 16 + h * 8 + lrow;
            if (r >= S_) continue;
            float* orow = O + (size_t)r * 64;
            #pragma unroll
            for (int nj = 0; nj < 4; ++nj) {
                int cg = wn * 32 + nj * 8 + lcol;
                float2 o = *(float2*)(orow + cg);
                o.x += acc[mi * 4 + nj][h * 2];
                o.y += acc[mi * 4 + nj][h * 2 + 1];
                *(float2*)(orow + cg) = o;
            }
        }
    }
}

// ---------------------------------------------------------------------------
extern "C" void kernel_launch(void* const* d_in, const int* in_sizes, int n_in,
                              void* d_out, int out_size)
{
    const float* pq  = (const float*)d_in[0];
    const float* pk  = (const float*)d_in[1];
    const float* pvv = (const float*)d_in[2];
    const float* tq  = (const float*)d_in[3];
    const float* tk  = (const float*)d_in[4];
    const float* tvv = (const float*)d_in[5];
    const float* dq  = (const float*)d_in[6];
    const float* dk  = (const float*)d_in[7];
    const float* dvv = (const float*)d_in[8];
    const int*   msk = (const int*)d_in[9];
    float* out = (float*)d_out;

    cudaFuncSetAttribute(qk_kernel,   cudaFuncAttributeMaxDynamicSharedMemorySize, 69632);
    cudaFuncSetAttribute(pv_a_kernel, cudaFuncAttributeMaxDynamicSharedMemorySize, 55296);
    cudaFuncSetAttribute(pv_b_kernel, cudaFuncAttributeMaxDynamicSharedMemorySize, 92160);

    convert_kernel<<<6144, 256>>>(pq, pk, pvv, tq, tk, tvv, dq, dk, dvv);
    qk_kernel<<<dim3(16, 16, 48), 512, 69632>>>();
    softmax_kernel<<<dim3(2048, 48), 256>>>(msk, out);
    pv_a_kernel<<<dim3(16, 1, 48), 256, 55296>>>(out);
    pv_b_kernel<<<dim3(16, 1, 16), 256, 92160>>>(out);
}

// round 16
// speedup vs baseline: 1.3179x; 1.3179x over previous
#include <cuda_runtime.h>
#include <cuda_bf16.h>
#include <cuda_fp16.h>
#include <cstdint>

#define S_   2048
#define SM_  2047
#define NEGV (-1e9f)

// Output layout (floats): poi, time, dist, attn1, attn2, attn3
#define O_POI   ((size_t)0)
#define O_TIME  ((size_t)2097152)
#define O_DIST  ((size_t)4193280)
#define O_A1    ((size_t)6289408)
#define O_A2    ((size_t)73398272)
#define O_A3    ((size_t)140441616)

// fp16 logits / softmax scratch: [z][2048][2048], zero padded
__device__ __align__(16) __half g_p[(size_t)3 * 16 * 2048 * 2048];
// pre-split Q,K: [z][2048 rows][ qh(64) | ql(64) ] bf16, zero padded rows
__device__ __align__(16) __nv_bfloat16 g_q[(size_t)48 * 2048 * 128];
__device__ __align__(16) __nv_bfloat16 g_k[(size_t)48 * 2048 * 128];
// V fp16: [z][2048 rows][64], zero padded rows
__device__ __align__(16) __half g_v[(size_t)48 * 2048 * 64];

// ---------------- helpers ----------------
__device__ __forceinline__ uint32_t smem_u32(const void* p) {
    uint32_t a;
    asm("{ .reg .u64 t; cvta.to.shared.u64 t, %1; cvt.u32.u64 %0, t; }" : "=r"(a) : "l"(p));
    return a;
}
__device__ __forceinline__ void cpa16(uint32_t d, const void* g) {
    asm volatile("cp.async.cg.shared.global [%0], [%1], 16;" :: "r"(d), "l"(g));
}
__device__ __forceinline__ void cpa_commit() {
    asm volatile("cp.async.commit_group;");
}
__device__ __forceinline__ void cpa_wait_all() {
    asm volatile("cp.async.commit_group;");
    asm volatile("cp.async.wait_group 0;");
}
__device__ __forceinline__ void ldm4(uint32_t* r, uint32_t addr) {
    asm volatile("ldmatrix.sync.aligned.m8n8.x4.shared.b16 {%0,%1,%2,%3}, [%4];"
                 : "=r"(r[0]), "=r"(r[1]), "=r"(r[2]), "=r"(r[3]) : "r"(addr));
}
__device__ __forceinline__ void ldm4t(uint32_t* r, uint32_t addr) {
    asm volatile("ldmatrix.sync.aligned.m8n8.x4.trans.shared.b16 {%0,%1,%2,%3}, [%4];"
                 : "=r"(r[0]), "=r"(r[1]), "=r"(r[2]), "=r"(r[3]) : "r"(addr));
}
__device__ __forceinline__ void mma_bf16(float* c, const uint32_t* a, const uint32_t* b) {
    asm volatile("mma.sync.aligned.m16n8k16.row.col.f32.bf16.bf16.f32 "
                 "{%0,%1,%2,%3}, {%4,%5,%6,%7}, {%8,%9}, {%0,%1,%2,%3};"
                 : "+f"(c[0]), "+f"(c[1]), "+f"(c[2]), "+f"(c[3])
                 : "r"(a[0]), "r"(a[1]), "r"(a[2]), "r"(a[3]), "r"(b[0]), "r"(b[1]));
}
__device__ __forceinline__ void mma_f16(float* c, const uint32_t* a, const uint32_t* b) {
    asm volatile("mma.sync.aligned.m16n8k16.row.col.f32.f16.f16.f32 "
                 "{%0,%1,%2,%3}, {%4,%5,%6,%7}, {%8,%9}, {%0,%1,%2,%3};"
                 : "+f"(c[0]), "+f"(c[1]), "+f"(c[2]), "+f"(c[3])
                 : "r"(a[0]), "r"(a[1]), "r"(a[2]), "r"(a[3]), "r"(b[0]), "r"(b[1]));
}
__device__ __forceinline__ void split2(float a, float b, uint32_t& hi, uint32_t& lo) {
    __nv_bfloat16 ha = __float2bfloat16(a), hb = __float2bfloat16(b);
    float la = a - __bfloat162float(ha), lb = b - __bfloat162float(hb);
    __nv_bfloat162 hh; hh.x = ha; hh.y = hb;
    hi = *reinterpret_cast<uint32_t*>(&hh);
    __nv_bfloat162 ll = __floats2bfloat162_rn(la, lb);
    lo = *reinterpret_cast<uint32_t*>(&ll);
}
__device__ __forceinline__ uint32_t ph2(float a, float b) {
    __half2 h = __floats2half2_rn(a, b);
    return *reinterpret_cast<uint32_t*>(&h);
}

// ---------------------------------------------------------------------------
// K0: conversion (unchanged).
// ---------------------------------------------------------------------------
__global__ __launch_bounds__(256) void convert_kernel(
    const float* __restrict__ pq, const float* __restrict__ pk, const float* __restrict__ pvv,
    const float* __restrict__ tq, const float* __restrict__ tk, const float* __restrict__ tvv,
    const float* __restrict__ dq, const float* __restrict__ dk, const float* __restrict__ dvv)
{
    int gid = blockIdx.x * 256 + threadIdx.x;
    int c4  = gid & 15;
    int row = (gid >> 4) & 2047;
    int z   = gid >> 15;
    int s = z >> 4, bh = z & 15;

    const float *q, *k, *v;
    int Sq;
    if (s == 0)      { q = pq; k = pk; v = pvv; Sq = S_;  }
    else if (s == 1) { q = tq; k = tk; v = tvv; Sq = SM_; }
    else             { q = dq; k = dk; v = dvv; Sq = SM_; }

    float4 qv = make_float4(0.f,0.f,0.f,0.f), kv = qv, vv = qv;
    if (row < Sq) {
        size_t in = ((size_t)bh * Sq + row) * 64 + c4 * 4;
        qv = *(const float4*)(q + in);
        kv = *(const float4*)(k + in);
        vv = *(const float4*)(v + in);
        qv.x *= 0.125f; qv.y *= 0.125f; qv.z *= 0.125f; qv.w *= 0.125f;
    }
    size_t base = ((size_t)z * 2048 + row) * 128 + c4 * 4;
    uint32_t h01, h23, l01, l23;
    split2(qv.x, qv.y, h01, l01); split2(qv.z, qv.w, h23, l23);
    *(uint2*)(g_q + base)      = make_uint2(h01, h23);
    *(uint2*)(g_q + base + 64) = make_uint2(l01, l23);
    split2(kv.x, kv.y, h01, l01); split2(kv.z, kv.w, h23, l23);
    *(uint2*)(g_k + base)      = make_uint2(h01, h23);
    *(uint2*)(g_k + base + 64) = make_uint2(l01, l23);
    *(uint2*)(g_v + ((size_t)z * 2048 + row) * 64 + c4 * 4) =
        make_uint2(ph2(vv.x, vv.y), ph2(vv.z, vv.w));
}

// ---------------------------------------------------------------------------
// K1: logits -> fp16 g_p. R13 structure (256 thr, 8 warps 4x2, 128x128 tile),
// NEW epilogue: fragments -> smem (288B row stride) -> coalesced uint4 stores.
// ---------------------------------------------------------------------------
__global__ __launch_bounds__(256, 2) void qk_kernel()
{
    extern __shared__ __align__(16) char smc[];
    const uint32_t sb = smem_u32(smc);
    const uint32_t sbB = sb + 34816;

    const int tid = threadIdx.x, lid = tid & 31, wid = tid >> 5;
    const int z = blockIdx.z, s = z >> 4;
    const int Sq = s ? SM_ : S_;
    const int m0 = blockIdx.y * 128, n0 = blockIdx.x * 128;

    __half* Pout = g_p + ((size_t)z << 22);
    const __nv_bfloat16* Qs = g_q + ((size_t)z * 2048 + m0) * 128;
    const __nv_bfloat16* Ks = g_k + ((size_t)z * 2048 + n0) * 128;

    #pragma unroll
    for (int it = 0; it < 8; ++it) {
        int i = it * 256 + tid;
        int r = i >> 4, c = i & 15;
        cpa16(sb  + r * 272 + c * 16, Qs + (size_t)r * 128 + c * 8);
        cpa16(sbB + r * 272 + c * 16, Ks + (size_t)r * 128 + c * 8);
    }
    cpa_wait_all();
    __syncthreads();

    const int wm = wid & 3, wn = wid >> 2;
    float acc[16][4];
    #pragma unroll
    for (int t = 0; t < 16; ++t)
        #pragma unroll
        for (int j = 0; j < 4; ++j) acc[t][j] = 0.f;

    #pragma unroll
    for (int term = 0; term < 3; ++term) {
        const uint32_t aoff = (term == 2) ? 128u : 0u;
        const uint32_t boff = (term == 1) ? 128u : 0u;
        #pragma unroll
        for (int ks = 0; ks < 4; ++ks) {
            uint32_t a[2][4];
            #pragma unroll
            for (int mi = 0; mi < 2; ++mi) {
                int row = wm * 32 + mi * 16 + (lid & 15);
                ldm4(a[mi], sb + row * 272 + aoff + ks * 32 + ((lid >> 4) << 4));
            }
            uint32_t b[8][2];
            #pragma unroll
            for (int nb2 = 0; nb2 < 4; ++nb2) {
                int row = wn * 64 + nb2 * 16 + ((lid >> 4) << 3) + (lid & 7);
                uint32_t r4[4];
                ldm4(r4, sbB + row * 272 + boff + ks * 32 + (((lid >> 3) & 1) << 4));
                b[nb2 * 2][0] = r4[0]; b[nb2 * 2][1] = r4[1];
                b[nb2 * 2 + 1][0] = r4[2]; b[nb2 * 2 + 1][1] = r4[3];
            }
            #pragma unroll
            for (int mi = 0; mi < 2; ++mi)
                #pragma unroll
                for (int nj = 0; nj < 8; ++nj)
                    mma_bf16(acc[mi * 8 + nj], a[mi], b[nj]);
        }
    }

    // ---- epilogue: bounce tile (fp16) through smem, then coalesced stores ----
    __syncthreads();   // all warps done reading A/B smem

    const int lrow = lid >> 2, lcol = (lid & 3) * 2;
    #pragma unroll
    for (int mi = 0; mi < 2; ++mi) {
        #pragma unroll
        for (int h = 0; h < 2; ++h) {
            int rloc = wm * 32 + mi * 16 + h * 8 + lrow;
            #pragma unroll
            for (int nj = 0; nj < 8; ++nj) {
                int cloc = wn * 64 + nj * 8 + lcol;
                *(uint32_t*)(smc + rloc * 288 + cloc * 2) =
                    ph2(acc[mi * 8 + nj][h * 2], acc[mi * 8 + nj][h * 2 + 1]);
            }
        }
    }
    __syncthreads();

    #pragma unroll
    for (int it = 0; it < 8; ++it) {
        int i = it * 256 + tid;          // 2048 = 128 rows x 16 chunks of 16B
        int r = i >> 4, c = i & 15;
        int q = m0 + r;
        if (q < Sq)
            *(uint4*)(Pout + ((size_t)q << 11) + n0 + c * 8) =
                *(const uint4*)(smc + r * 288 + c * 16);
    }
}

// ---------------------------------------------------------------------------
// K2: softmax (unchanged from R13).
// ---------------------------------------------------------------------------
__global__ __launch_bounds__(256) void softmax_kernel(
    const int* __restrict__ mask, float* __restrict__ out)
{
    const int row = blockIdx.x, z = blockIdx.y, stream = z >> 4, bh = z & 15;
    int Sk; float* A;
    if (stream == 0)      { Sk = S_;  A = out + O_A1 + (size_t)bh * S_  * S_;  }
    else if (stream == 1) { Sk = SM_; A = out + O_A2 + (size_t)bh * SM_ * SM_; }
    else                  { Sk = SM_; A = out + O_A3 + (size_t)bh * SM_ * SM_; }

    const int tid = threadIdx.x;
    __half* r16 = g_p + ((size_t)z << 22) + ((size_t)row << 11);

    if (row >= Sk) {
        ((uint4*)r16)[tid] = make_uint4(0, 0, 0, 0);
        return;
    }

    float* r = A + (size_t)row * Sk;
    const bool vec = (stream == 0);
    const int i0 = tid * 8;
    float v[8];
    if (vec) {
        uint4 hv = *(const uint4*)(r16 + i0);
        const __half2* hp = (const __half2*)&hv;
        #pragma unroll
        for (int u = 0; u < 4; ++u) {
            float2 f = __half22float2(hp[u]);
            v[u * 2] = f.x; v[u * 2 + 1] = f.y;
        }
        const int* Mrow = mask + ((size_t)(bh >> 3) << 22) + ((size_t)row << 11) + i0;
        int4 ma = *(const int4*)Mrow;
        int4 mb = *(const int4*)(Mrow + 4);
        if (!ma.x) v[0] = NEGV; if (!ma.y) v[1] = NEGV;
        if (!ma.z) v[2] = NEGV; if (!ma.w) v[3] = NEGV;
        if (!mb.x) v[4] = NEGV; if (!mb.y) v[5] = NEGV;
        if (!mb.z) v[6] = NEGV; if (!mb.w) v[7] = NEGV;
    } else {
        #pragma unroll
        for (int u = 0; u < 8; ++u) {
            int i = u * 256 + tid;
            v[u] = (i < Sk) ? __half2float(r16[i]) : -3.0e38f;
        }
    }

    float m = v[0];
    #pragma unroll
    for (int u = 1; u < 8; ++u) m = fmaxf(m, v[u]);
    #pragma unroll
    for (int o = 16; o > 0; o >>= 1) m = fmaxf(m, __shfl_xor_sync(0xffffffffu, m, o));
    __shared__ float smr[8];
    const int w = tid >> 5, l = tid & 31;
    if (l == 0) smr[w] = m;
    __syncthreads();
    if (tid < 32) {
        float t = (tid < 8) ? smr[tid] : -3.0e38f;
        #pragma unroll
        for (int o = 4; o > 0; o >>= 1) t = fmaxf(t, __shfl_xor_sync(0xffffffffu, t, o));
        if (tid == 0) smr[0] = t;
    }
    __syncthreads();
    m = smr[0];
    __syncthreads();
    float sacc = 0.f;
    #pragma unroll
    for (int u = 0; u < 8; ++u) { v[u] = __expf(v[u] - m); sacc += v[u]; }
    #pragma unroll
    for (int o = 16; o > 0; o >>= 1) sacc += __shfl_xor_sync(0xffffffffu, sacc, o);
    if (l == 0) smr[w] = sacc;
    __syncthreads();
    if (tid < 32) {
        float t = (tid < 8) ? smr[tid] : 0.f;
        #pragma unroll
        for (int o = 4; o > 0; o >>= 1) t += __shfl_xor_sync(0xffffffffu, t, o);
        if (tid == 0) smr[0] = t;
    }
    __syncthreads();
    const float inv = 1.0f / smr[0];
    #pragma unroll
    for (int u = 0; u < 8; ++u) v[u] *= inv;

    if (vec) {
        *(float4*)(r + i0)     = make_float4(v[0], v[1], v[2], v[3]);
        *(float4*)(r + i0 + 4) = make_float4(v[4], v[5], v[6], v[7]);
        uint4 hw;
        hw.x = ph2(v[0], v[1]); hw.y = ph2(v[2], v[3]);
        hw.z = ph2(v[4], v[5]); hw.w = ph2(v[6], v[7]);
        *(uint4*)(r16 + i0) = hw;
    } else {
        #pragma unroll
        for (int u = 0; u < 8; ++u) {
            int i = u * 256 + tid;
            r16[i] = __float2half_rn(v[u]);
            if (i < Sk) r[i] = v[u];
        }
    }
}

// ---------------------------------------------------------------------------
// K3: O = P @ V via fp16 mma.sync (proven R13/R10 version, single kernel).
// ---------------------------------------------------------------------------
__global__ __launch_bounds__(256, 2) void pv_kernel(float* __restrict__ out)
{
    __shared__ __align__(16) __half A1s[128][72];
    __shared__ __align__(16) __half A2s[128][72];
    __shared__ __align__(16) __half Vss[64][72];

    const int tid = threadIdx.x, lid = tid & 31, wid = tid >> 5;
    const int z = blockIdx.z, jt = z >> 4, bh = z & 15;
    const int m0 = blockIdx.x * 128;

    const __half* P1h = g_p + ((size_t)(jt * 16 + bh) << 22);
    const __half* P2h = g_p + ((size_t)(16 + bh) << 22);
    const __half* P3h = g_p + ((size_t)(32 + bh) << 22);
    const __half* Vh  = g_v + ((size_t)(jt * 16 + bh) << 17);

    float* O;
    int Sq;
    if (jt == 0)      { O = out + O_POI  + (size_t)bh * S_  * 64; Sq = S_;  }
    else if (jt == 1) { O = out + O_TIME + (size_t)bh * SM_ * 64; Sq = SM_; }
    else              { O = out + O_DIST + (size_t)bh * SM_ * 64; Sq = SM_; }

    const uint32_t uA1 = smem_u32(A1s), uA2 = smem_u32(A2s), uV = smem_u32(Vss);
    const int wm = wid & 3, wn = wid >> 2;

    float acc[8][4];
    #pragma unroll
    for (int t = 0; t < 8; ++t)
        #pragma unroll
        for (int j = 0; j < 4; ++j) acc[t][j] = 0.f;

    for (int ck = 0; ck < 2048; ck += 64) {
        #pragma unroll
        for (int it = 0; it < 4; ++it) {
            int i = it * 256 + tid;
            int row = i >> 3, c8 = i & 7;
            cpa16(uA1 + row * 144 + c8 * 16,
                  P1h + (((size_t)(m0 + row)) << 11) + ck + c8 * 8);
        }
        #pragma unroll
        for (int it = 0; it < 2; ++it) {
            int i = it * 256 + tid;
            int row = i >> 3, c8 = i & 7;
            cpa16(uV + row * 144 + c8 * 16,
                  Vh + (size_t)(ck + row) * 64 + c8 * 8);
        }
        if (jt == 0) {
            #pragma unroll
            for (int it = 0; it < 4; ++it) {
                int i = it * 256 + tid;
                int row = i >> 3, col8 = (i & 7) << 3;
                uint4 res = make_uint4(0, 0, 0, 0);
                if (m0 + row > 0) {
                    size_t off = (((size_t)(m0 + row - 1)) << 11) + ck + col8;
                    uint4 a = *(const uint4*)(P2h + off);
                    uint4 b = *(const uint4*)(P3h + off);
                    __half2* ah = (__half2*)&a; __half2* bh2 = (__half2*)&b;
                    __half2* rh = (__half2*)&res;
                    #pragma unroll
                    for (int j = 0; j < 4; ++j) rh[j] = __hadd2(ah[j], bh2[j]);
                }
                *(uint4*)&A2s[row][col8] = res;
            }
        }
        cpa_wait_all();
        __syncthreads();

        #pragma unroll
        for (int ks = 0; ks < 4; ++ks) {
            uint32_t b[4][2];
            #pragma unroll
            for (int nb2 = 0; nb2 < 2; ++nb2) {
                int krow = ks * 16 + (((lid >> 3) & 1) << 3) + (lid & 7);
                int ncol = wn * 32 + nb2 * 16 + ((lid >> 4) << 3);
                uint32_t r4[4];
                ldm4t(r4, uV + krow * 144 + ncol * 2);
                b[nb2 * 2][0] = r4[0]; b[nb2 * 2][1] = r4[1];
                b[nb2 * 2 + 1][0] = r4[2]; b[nb2 * 2 + 1][1] = r4[3];
            }
            uint32_t a[2][4];
            #pragma unroll
            for (int mi = 0; mi < 2; ++mi) {
                int row = wm * 32 + mi * 16 + (lid & 15);
                ldm4(a[mi], uA1 + row * 144 + ks * 32 + ((lid >> 4) << 4));
            }
            #pragma unroll
            for (int mi = 0; mi < 2; ++mi)
                #pragma unroll
                for (int nj = 0; nj < 4; ++nj)
                    mma_f16(acc[mi * 4 + nj], a[mi], b[nj]);
            if (jt == 0) {
                #pragma unroll
                for (int mi = 0; mi < 2; ++mi) {
                    int row = wm * 32 + mi * 16 + (lid & 15);
                    ldm4(a[mi], uA2 + row * 144 + ks * 32 + ((lid >> 4) << 4));
                }
                #pragma unroll
                for (int mi = 0; mi < 2; ++mi)
                    #pragma unroll
                    for (int nj = 0; nj < 4; ++nj)
                        mma_f16(acc[mi * 4 + nj], a[mi], b[nj]);
            }
        }
        __syncthreads();
    }

    const int lrow = lid >> 2, lcol = (lid & 3) * 2;
    #pragma unroll
    for (int mi = 0; mi < 2; ++mi) {
        #pragma unroll
        for (int h = 0; h < 2; ++h) {
            int r = m0 + wm * 32 + mi * 16 + h * 8 + lrow;
            if (r >= Sq) continue;
            float* orow = O + (size_t)r * 64;
            #pragma unroll
            for (int nj = 0; nj < 4; ++nj) {
                int cg = wn * 32 + nj * 8 + lcol;
                *(float2*)(orow + cg) =
                    make_float2(acc[mi * 4 + nj][h * 2], acc[mi * 4 + nj][h * 2 + 1]);
            }
        }
    }
}

// ---------------------------------------------------------------------------
extern "C" void kernel_launch(void* const* d_in, const int* in_sizes, int n_in,
                              void* d_out, int out_size)
{
    const float* pq  = (const float*)d_in[0];
    const float* pk  = (const float*)d_in[1];
    const float* pvv = (const float*)d_in[2];
    const float* tq  = (const float*)d_in[3];
    const float* tk  = (const float*)d_in[4];
    const float* tvv = (const float*)d_in[5];
    const float* dq  = (const float*)d_in[6];
    const float* dk  = (const float*)d_in[7];
    const float* dvv = (const float*)d_in[8];
    const int*   msk = (const int*)d_in[9];
    float* out = (float*)d_out;

    cudaFuncSetAttribute(qk_kernel, cudaFuncAttributeMaxDynamicSharedMemorySize, 69632);

    convert_kernel<<<6144, 256>>>(pq, pk, pvv, tq, tk, tvv, dq, dk, dvv);
    qk_kernel<<<dim3(16, 16, 48), 256, 69632>>>();
    softmax_kernel<<<dim3(2048, 48), 256>>>(msk, out);
    pv_kernel<<<dim3(16, 1, 48), 256>>>(out);
}

// round 17
// speedup vs baseline: 1.3195x; 1.0013x over previous
#include <cuda_runtime.h>
#include <cuda_bf16.h>
#include <cuda_fp16.h>
#include <cstdint>

#define S_   2048
#define SM_  2047
#define NEGV (-1e9f)

// Output layout (floats): poi, time, dist, attn1, attn2, attn3
#define O_POI   ((size_t)0)
#define O_TIME  ((size_t)2097152)
#define O_DIST  ((size_t)4193280)
#define O_A1    ((size_t)6289408)
#define O_A2    ((size_t)73398272)
#define O_A3    ((size_t)140441616)

// fp16 logits / softmax scratch: [z][2048][2048], zero padded
__device__ __align__(16) __half g_p[(size_t)3 * 16 * 2048 * 2048];
// pre-split Q,K: [z][2048 rows][ qh(64) | ql(64) ] bf16, zero padded rows
__device__ __align__(16) __nv_bfloat16 g_q[(size_t)48 * 2048 * 128];
__device__ __align__(16) __nv_bfloat16 g_k[(size_t)48 * 2048 * 128];
// V fp16: [z][2048 rows][64], zero padded rows
__device__ __align__(16) __half g_v[(size_t)48 * 2048 * 64];

// ---------------- helpers ----------------
__device__ __forceinline__ uint32_t smem_u32(const void* p) {
    uint32_t a;
    asm("{ .reg .u64 t; cvta.to.shared.u64 t, %1; cvt.u32.u64 %0, t; }" : "=r"(a) : "l"(p));
    return a;
}
__device__ __forceinline__ void cpa16(uint32_t d, const void* g) {
    asm volatile("cp.async.cg.shared.global [%0], [%1], 16;" :: "r"(d), "l"(g));
}
__device__ __forceinline__ void cpa_commit() {
    asm volatile("cp.async.commit_group;");
}
__device__ __forceinline__ void cpa_wait_all() {
    asm volatile("cp.async.commit_group;");
    asm volatile("cp.async.wait_group 0;");
}
__device__ __forceinline__ void ldm4(uint32_t* r, uint32_t addr) {
    asm volatile("ldmatrix.sync.aligned.m8n8.x4.shared.b16 {%0,%1,%2,%3}, [%4];"
                 : "=r"(r[0]), "=r"(r[1]), "=r"(r[2]), "=r"(r[3]) : "r"(addr));
}
__device__ __forceinline__ void ldm4t(uint32_t* r, uint32_t addr) {
    asm volatile("ldmatrix.sync.aligned.m8n8.x4.trans.shared.b16 {%0,%1,%2,%3}, [%4];"
                 : "=r"(r[0]), "=r"(r[1]), "=r"(r[2]), "=r"(r[3]) : "r"(addr));
}
__device__ __forceinline__ void mma_bf16(float* c, const uint32_t* a, const uint32_t* b) {
    asm volatile("mma.sync.aligned.m16n8k16.row.col.f32.bf16.bf16.f32 "
                 "{%0,%1,%2,%3}, {%4,%5,%6,%7}, {%8,%9}, {%0,%1,%2,%3};"
                 : "+f"(c[0]), "+f"(c[1]), "+f"(c[2]), "+f"(c[3])
                 : "r"(a[0]), "r"(a[1]), "r"(a[2]), "r"(a[3]), "r"(b[0]), "r"(b[1]));
}
__device__ __forceinline__ void mma_f16(float* c, const uint32_t* a, const uint32_t* b) {
    asm volatile("mma.sync.aligned.m16n8k16.row.col.f32.f16.f16.f32 "
                 "{%0,%1,%2,%3}, {%4,%5,%6,%7}, {%8,%9}, {%0,%1,%2,%3};"
                 : "+f"(c[0]), "+f"(c[1]), "+f"(c[2]), "+f"(c[3])
                 : "r"(a[0]), "r"(a[1]), "r"(a[2]), "r"(a[3]), "r"(b[0]), "r"(b[1]));
}
__device__ __forceinline__ void split2(float a, float b, uint32_t& hi, uint32_t& lo) {
    __nv_bfloat16 ha = __float2bfloat16(a), hb = __float2bfloat16(b);
    float la = a - __bfloat162float(ha), lb = b - __bfloat162float(hb);
    __nv_bfloat162 hh; hh.x = ha; hh.y = hb;
    hi = *reinterpret_cast<uint32_t*>(&hh);
    __nv_bfloat162 ll = __floats2bfloat162_rn(la, lb);
    lo = *reinterpret_cast<uint32_t*>(&ll);
}
__device__ __forceinline__ uint32_t ph2(float a, float b) {
    __half2 h = __floats2half2_rn(a, b);
    return *reinterpret_cast<uint32_t*>(&h);
}

// ---------------------------------------------------------------------------
// K0: conversion (unchanged).
// ---------------------------------------------------------------------------
__global__ __launch_bounds__(256) void convert_kernel(
    const float* __restrict__ pq, const float* __restrict__ pk, const float* __restrict__ pvv,
    const float* __restrict__ tq, const float* __restrict__ tk, const float* __restrict__ tvv,
    const float* __restrict__ dq, const float* __restrict__ dk, const float* __restrict__ dvv)
{
    int gid = blockIdx.x * 256 + threadIdx.x;
    int c4  = gid & 15;
    int row = (gid >> 4) & 2047;
    int z   = gid >> 15;
    int s = z >> 4, bh = z & 15;

    const float *q, *k, *v;
    int Sq;
    if (s == 0)      { q = pq; k = pk; v = pvv; Sq = S_;  }
    else if (s == 1) { q = tq; k = tk; v = tvv; Sq = SM_; }
    else             { q = dq; k = dk; v = dvv; Sq = SM_; }

    float4 qv = make_float4(0.f,0.f,0.f,0.f), kv = qv, vv = qv;
    if (row < Sq) {
        size_t in = ((size_t)bh * Sq + row) * 64 + c4 * 4;
        qv = *(const float4*)(q + in);
        kv = *(const float4*)(k + in);
        vv = *(const float4*)(v + in);
        qv.x *= 0.125f; qv.y *= 0.125f; qv.z *= 0.125f; qv.w *= 0.125f;
    }
    size_t base = ((size_t)z * 2048 + row) * 128 + c4 * 4;
    uint32_t h01, h23, l01, l23;
    split2(qv.x, qv.y, h01, l01); split2(qv.z, qv.w, h23, l23);
    *(uint2*)(g_q + base)      = make_uint2(h01, h23);
    *(uint2*)(g_q + base + 64) = make_uint2(l01, l23);
    split2(kv.x, kv.y, h01, l01); split2(kv.z, kv.w, h23, l23);
    *(uint2*)(g_k + base)      = make_uint2(h01, h23);
    *(uint2*)(g_k + base + 64) = make_uint2(l01, l23);
    *(uint2*)(g_v + ((size_t)z * 2048 + row) * 64 + c4 * 4) =
        make_uint2(ph2(vv.x, vv.y), ph2(vv.z, vv.w));
}

// ---------------------------------------------------------------------------
// K1: logits -> fp16 g_p. R13 structure (256 thr, 8 warps 4x2, 128x128 tile),
// NEW epilogue: fragments -> smem (288B row stride) -> coalesced uint4 stores.
// ---------------------------------------------------------------------------
__global__ __launch_bounds__(256, 2) void qk_kernel()
{
    extern __shared__ __align__(16) char smc[];
    const uint32_t sb = smem_u32(smc);
    const uint32_t sbB = sb + 34816;

    const int tid = threadIdx.x, lid = tid & 31, wid = tid >> 5;
    const int z = blockIdx.z, s = z >> 4;
    const int Sq = s ? SM_ : S_;
    const int m0 = blockIdx.y * 128, n0 = blockIdx.x * 128;

    __half* Pout = g_p + ((size_t)z << 22);
    const __nv_bfloat16* Qs = g_q + ((size_t)z * 2048 + m0) * 128;
    const __nv_bfloat16* Ks = g_k + ((size_t)z * 2048 + n0) * 128;

    #pragma unroll
    for (int it = 0; it < 8; ++it) {
        int i = it * 256 + tid;
        int r = i >> 4, c = i & 15;
        cpa16(sb  + r * 272 + c * 16, Qs + (size_t)r * 128 + c * 8);
        cpa16(sbB + r * 272 + c * 16, Ks + (size_t)r * 128 + c * 8);
    }
    cpa_wait_all();
    __syncthreads();

    const int wm = wid & 3, wn = wid >> 2;
    float acc[16][4];
    #pragma unroll
    for (int t = 0; t < 16; ++t)
        #pragma unroll
        for (int j = 0; j < 4; ++j) acc[t][j] = 0.f;

    #pragma unroll
    for (int term = 0; term < 3; ++term) {
        const uint32_t aoff = (term == 2) ? 128u : 0u;
        const uint32_t boff = (term == 1) ? 128u : 0u;
        #pragma unroll
        for (int ks = 0; ks < 4; ++ks) {
            uint32_t a[2][4];
            #pragma unroll
            for (int mi = 0; mi < 2; ++mi) {
                int row = wm * 32 + mi * 16 + (lid & 15);
                ldm4(a[mi], sb + row * 272 + aoff + ks * 32 + ((lid >> 4) << 4));
            }
            uint32_t b[8][2];
            #pragma unroll
            for (int nb2 = 0; nb2 < 4; ++nb2) {
                int row = wn * 64 + nb2 * 16 + ((lid >> 4) << 3) + (lid & 7);
                uint32_t r4[4];
                ldm4(r4, sbB + row * 272 + boff + ks * 32 + (((lid >> 3) & 1) << 4));
                b[nb2 * 2][0] = r4[0]; b[nb2 * 2][1] = r4[1];
                b[nb2 * 2 + 1][0] = r4[2]; b[nb2 * 2 + 1][1] = r4[3];
            }
            #pragma unroll
            for (int mi = 0; mi < 2; ++mi)
                #pragma unroll
                for (int nj = 0; nj < 8; ++nj)
                    mma_bf16(acc[mi * 8 + nj], a[mi], b[nj]);
        }
    }

    // ---- epilogue: bounce tile (fp16) through smem, then coalesced stores ----
    __syncthreads();   // all warps done reading A/B smem

    const int lrow = lid >> 2, lcol = (lid & 3) * 2;
    #pragma unroll
    for (int mi = 0; mi < 2; ++mi) {
        #pragma unroll
        for (int h = 0; h < 2; ++h) {
            int rloc = wm * 32 + mi * 16 + h * 8 + lrow;
            #pragma unroll
            for (int nj = 0; nj < 8; ++nj) {
                int cloc = wn * 64 + nj * 8 + lcol;
                *(uint32_t*)(smc + rloc * 288 + cloc * 2) =
                    ph2(acc[mi * 8 + nj][h * 2], acc[mi * 8 + nj][h * 2 + 1]);
            }
        }
    }
    __syncthreads();

    #pragma unroll
    for (int it = 0; it < 8; ++it) {
        int i = it * 256 + tid;          // 2048 = 128 rows x 16 chunks of 16B
        int r = i >> 4, c = i & 15;
        int q = m0 + r;
        if (q < Sq)
            *(uint4*)(Pout + ((size_t)q << 11) + n0 + c * 8) =
                *(const uint4*)(smc + r * 288 + c * 16);
    }
}

// ---------------------------------------------------------------------------
// K2: softmax (unchanged from R13).
// ---------------------------------------------------------------------------
__global__ __launch_bounds__(256) void softmax_kernel(
    const int* __restrict__ mask, float* __restrict__ out)
{
    const int row = blockIdx.x, z = blockIdx.y, stream = z >> 4, bh = z & 15;
    int Sk; float* A;
    if (stream == 0)      { Sk = S_;  A = out + O_A1 + (size_t)bh * S_  * S_;  }
    else if (stream == 1) { Sk = SM_; A = out + O_A2 + (size_t)bh * SM_ * SM_; }
    else                  { Sk = SM_; A = out + O_A3 + (size_t)bh * SM_ * SM_; }

    const int tid = threadIdx.x;
    __half* r16 = g_p + ((size_t)z << 22) + ((size_t)row << 11);

    if (row >= Sk) {
        ((uint4*)r16)[tid] = make_uint4(0, 0, 0, 0);
        return;
    }

    float* r = A + (size_t)row * Sk;
    const bool vec = (stream == 0);
    const int i0 = tid * 8;
    float v[8];
    if (vec) {
        uint4 hv = *(const uint4*)(r16 + i0);
        const __half2* hp = (const __half2*)&hv;
        #pragma unroll
        for (int u = 0; u < 4; ++u) {
            float2 f = __half22float2(hp[u]);
            v[u * 2] = f.x; v[u * 2 + 1] = f.y;
        }
        const int* Mrow = mask + ((size_t)(bh >> 3) << 22) + ((size_t)row << 11) + i0;
        int4 ma = *(const int4*)Mrow;
        int4 mb = *(const int4*)(Mrow + 4);
        if (!ma.x) v[0] = NEGV; if (!ma.y) v[1] = NEGV;
        if (!ma.z) v[2] = NEGV; if (!ma.w) v[3] = NEGV;
        if (!mb.x) v[4] = NEGV; if (!mb.y) v[5] = NEGV;
        if (!mb.z) v[6] = NEGV; if (!mb.w) v[7] = NEGV;
    } else {
        #pragma unroll
        for (int u = 0; u < 8; ++u) {
            int i = u * 256 + tid;
            v[u] = (i < Sk) ? __half2float(r16[i]) : -3.0e38f;
        }
    }

    float m = v[0];
    #pragma unroll
    for (int u = 1; u < 8; ++u) m = fmaxf(m, v[u]);
    #pragma unroll
    for (int o = 16; o > 0; o >>= 1) m = fmaxf(m, __shfl_xor_sync(0xffffffffu, m, o));
    __shared__ float smr[8];
    const int w = tid >> 5, l = tid & 31;
    if (l == 0) smr[w] = m;
    __syncthreads();
    if (tid < 32) {
        float t = (tid < 8) ? smr[tid] : -3.0e38f;
        #pragma unroll
        for (int o = 4; o > 0; o >>= 1) t = fmaxf(t, __shfl_xor_sync(0xffffffffu, t, o));
        if (tid == 0) smr[0] = t;
    }
    __syncthreads();
    m = smr[0];
    __syncthreads();
    float sacc = 0.f;
    #pragma unroll
    for (int u = 0; u < 8; ++u) { v[u] = __expf(v[u] - m); sacc += v[u]; }
    #pragma unroll
    for (int o = 16; o > 0; o >>= 1) sacc += __shfl_xor_sync(0xffffffffu, sacc, o);
    if (l == 0) smr[w] = sacc;
    __syncthreads();
    if (tid < 32) {
        float t = (tid < 8) ? smr[tid] : 0.f;
        #pragma unroll
        for (int o = 4; o > 0; o >>= 1) t += __shfl_xor_sync(0xffffffffu, t, o);
        if (tid == 0) smr[0] = t;
    }
    __syncthreads();
    const float inv = 1.0f / smr[0];
    #pragma unroll
    for (int u = 0; u < 8; ++u) v[u] *= inv;

    if (vec) {
        *(float4*)(r + i0)     = make_float4(v[0], v[1], v[2], v[3]);
        *(float4*)(r + i0 + 4) = make_float4(v[4], v[5], v[6], v[7]);
        uint4 hw;
        hw.x = ph2(v[0], v[1]); hw.y = ph2(v[2], v[3]);
        hw.z = ph2(v[4], v[5]); hw.w = ph2(v[6], v[7]);
        *(uint4*)(r16 + i0) = hw;
    } else {
        #pragma unroll
        for (int u = 0; u < 8; ++u) {
            int i = u * 256 + tid;
            r16[i] = __float2half_rn(v[u]);
            if (i < Sk) r[i] = v[u];
        }
    }
}

// ---------------------------------------------------------------------------
// K3: O = P @ V via fp16 mma.sync (proven R13/R10 version, single kernel).
// ---------------------------------------------------------------------------
__global__ __launch_bounds__(256, 2) void pv_kernel(float* __restrict__ out)
{
    __shared__ __align__(16) __half A1s[128][72];
    __shared__ __align__(16) __half A2s[128][72];
    __shared__ __align__(16) __half Vss[64][72];

    const int tid = threadIdx.x, lid = tid & 31, wid = tid >> 5;
    const int z = blockIdx.z, jt = z >> 4, bh = z & 15;
    const int m0 = blockIdx.x * 128;

    const __half* P1h = g_p + ((size_t)(jt * 16 + bh) << 22);
    const __half* P2h = g_p + ((size_t)(16 + bh) << 22);
    const __half* P3h = g_p + ((size_t)(32 + bh) << 22);
    const __half* Vh  = g_v + ((size_t)(jt * 16 + bh) << 17);

    float* O;
    int Sq;
    if (jt == 0)      { O = out + O_POI  + (size_t)bh * S_  * 64; Sq = S_;  }
    else if (jt == 1) { O = out + O_TIME + (size_t)bh * SM_ * 64; Sq = SM_; }
    else              { O = out + O_DIST + (size_t)bh * SM_ * 64; Sq = SM_; }

    const uint32_t uA1 = smem_u32(A1s), uA2 = smem_u32(A2s), uV = smem_u32(Vss);
    const int wm = wid & 3, wn = wid >> 2;

    float acc[8][4];
    #pragma unroll
    for (int t = 0; t < 8; ++t)
        #pragma unroll
        for (int j = 0; j < 4; ++j) acc[t][j] = 0.f;

    for (int ck = 0; ck < 2048; ck += 64) {
        #pragma unroll
        for (int it = 0; it < 4; ++it) {
            int i = it * 256 + tid;
            int row = i >> 3, c8 = i & 7;
            cpa16(uA1 + row * 144 + c8 * 16,
                  P1h + (((size_t)(m0 + row)) << 11) + ck + c8 * 8);
        }
        #pragma unroll
        for (int it = 0; it < 2; ++it) {
            int i = it * 256 + tid;
            int row = i >> 3, c8 = i & 7;
            cpa16(uV + row * 144 + c8 * 16,
                  Vh + (size_t)(ck + row) * 64 + c8 * 8);
        }
        if (jt == 0) {
            #pragma unroll
            for (int it = 0; it < 4; ++it) {
                int i = it * 256 + tid;
                int row = i >> 3, col8 = (i & 7) << 3;
                uint4 res = make_uint4(0, 0, 0, 0);
                if (m0 + row > 0) {
                    size_t off = (((size_t)(m0 + row - 1)) << 11) + ck + col8;
                    uint4 a = *(const uint4*)(P2h + off);
                    uint4 b = *(const uint4*)(P3h + off);
                    __half2* ah = (__half2*)&a; __half2* bh2 = (__half2*)&b;
                    __half2* rh = (__half2*)&res;
                    #pragma unroll
                    for (int j = 0; j < 4; ++j) rh[j] = __hadd2(ah[j], bh2[j]);
                }
                *(uint4*)&A2s[row][col8] = res;
            }
        }
        cpa_wait_all();
        __syncthreads();

        #pragma unroll
        for (int ks = 0; ks < 4; ++ks) {
            uint32_t b[4][2];
            #pragma unroll
            for (int nb2 = 0; nb2 < 2; ++nb2) {
                int krow = ks * 16 + (((lid >> 3) & 1) << 3) + (lid & 7);
                int ncol = wn * 32 + nb2 * 16 + ((lid >> 4) << 3);
                uint32_t r4[4];
                ldm4t(r4, uV + krow * 144 + ncol * 2);
                b[nb2 * 2][0] = r4[0]; b[nb2 * 2][1] = r4[1];
                b[nb2 * 2 + 1][0] = r4[2]; b[nb2 * 2 + 1][1] = r4[3];
            }
            uint32_t a[2][4];
            #pragma unroll
            for (int mi = 0; mi < 2; ++mi) {
                int row = wm * 32 + mi * 16 + (lid & 15);
                ldm4(a[mi], uA1 + row * 144 + ks * 32 + ((lid >> 4) << 4));
            }
            #pragma unroll
            for (int mi = 0; mi < 2; ++mi)
                #pragma unroll
                for (int nj = 0; nj < 4; ++nj)
                    mma_f16(acc[mi * 4 + nj], a[mi], b[nj]);
            if (jt == 0) {
                #pragma unroll
                for (int mi = 0; mi < 2; ++mi) {
                    int row = wm * 32 + mi * 16 + (lid & 15);
                    ldm4(a[mi], uA2 + row * 144 + ks * 32 + ((lid >> 4) << 4));
                }
                #pragma unroll
                for (int mi = 0; mi < 2; ++mi)
                    #pragma unroll
                    for (int nj = 0; nj < 4; ++nj)
                        mma_f16(acc[mi * 4 + nj], a[mi], b[nj]);
            }
        }
        __syncthreads();
    }

    const int lrow = lid >> 2, lcol = (lid & 3) * 2;
    #pragma unroll
    for (int mi = 0; mi < 2; ++mi) {
        #pragma unroll
        for (int h = 0; h < 2; ++h) {
            int r = m0 + wm * 32 + mi * 16 + h * 8 + lrow;
            if (r >= Sq) continue;
            float* orow = O + (size_t)r * 64;
            #pragma unroll
            for (int nj = 0; nj < 4; ++nj) {
                int cg = wn * 32 + nj * 8 + lcol;
                *(float2*)(orow + cg) =
                    make_float2(acc[mi * 4 + nj][h * 2], acc[mi * 4 + nj][h * 2 + 1]);
            }
        }
    }
}

// ---------------------------------------------------------------------------
extern "C" void kernel_launch(void* const* d_in, const int* in_sizes, int n_in,
                              void* d_out, int out_size)
{
    const float* pq  = (const float*)d_in[0];
    const float* pk  = (const float*)d_in[1];
    const float* pvv = (const float*)d_in[2];
    const float* tq  = (const float*)d_in[3];
    const float* tk  = (const float*)d_in[4];
    const float* tvv = (const float*)d_in[5];
    const float* dq  = (const float*)d_in[6];
    const float* dk  = (const float*)d_in[7];
    const float* dvv = (const float*)d_in[8];
    const int*   msk = (const int*)d_in[9];
    float* out = (float*)d_out;

    cudaFuncSetAttribute(qk_kernel, cudaFuncAttributeMaxDynamicSharedMemorySize, 69632);

    convert_kernel<<<6144, 256>>>(pq, pk, pvv, tq, tk, tvv, dq, dk, dvv);
    qk_kernel<<<dim3(16, 16, 48), 256, 69632>>>();
    softmax_kernel<<<dim3(2048, 48), 256>>>(msk, out);
    pv_kernel<<<dim3(16, 1, 48), 256>>>(out);
}